// round 16
// baseline (speedup 1.0000x reference)
#include <cuda_runtime.h>

#define HH 40
#define WW 128
#define PP 5120
#define CC 128
#define KKN 25
#define SPOTN 5
#define NEGV (-1e8f)
#define FMAXV 3.402823466e38f
#define SENTK 0xffffffffffffffffull

// ---------------- scratch (device globals; no allocations allowed) ----------
__device__ float g_nimf[PP*CC];
__device__ float g_npcf[PP*CC];
__device__ float g_ahi[PP*CC];   // A fragments (imf) hi, mma-fragment layout
__device__ float g_alo[PP*CC];   // A fragments lo
__device__ float g_bhi[PP*CC];   // B fragments (pcf) hi
__device__ float g_blo[PP*CC];   // B fragments lo
__device__ float4 g_pts4[PP];    // padded points for vectorized knn
__device__ int   g_nb[PP*KKN];
__device__ unsigned long long g_rowbest[PP];
__device__ unsigned long long g_colbest[PP];
__device__ int   g_spot_im[PP*125];
__device__ int   g_spot_pc[PP*125];

__device__ __forceinline__ unsigned f2sort(float f){
    unsigned b = __float_as_uint(f);
    return (b & 0x80000000u) ? ~b : (b | 0x80000000u);
}
__device__ __forceinline__ float sort2f(unsigned u){
    unsigned b = (u & 0x80000000u) ? (u & 0x7fffffffu) : ~u;
    return __uint_as_float(b);
}
__device__ __forceinline__ int iclamp(int v, int lo, int hi){
    return v < lo ? lo : (v > hi ? hi : v);
}
__device__ __forceinline__ unsigned long long maxull(unsigned long long a, unsigned long long b){
    return a > b ? a : b;
}
__device__ __forceinline__ unsigned long long minull(unsigned long long a, unsigned long long b){
    return a < b ? a : b;
}
__device__ __forceinline__ float tf32r(float x){
    unsigned u; asm("cvt.rna.tf32.f32 %0, %1;" : "=r"(u) : "f"(x));
    return __uint_as_float(u);
}
__device__ __forceinline__ void cpasync16(unsigned s, const float* g){
    asm volatile("cp.async.cg.shared.global [%0], [%1], 16;\n" :: "r"(s), "l"(g));
}
#define KEYPACK(v,n) ((((unsigned long long)f2sort(v)) << 32) | (unsigned)(~(n)))

// ---------------- K1: L2 normalize both + argmax init ------------------------
__global__ __launch_bounds__(256) void k_norm(const float* __restrict__ imf,
                                              const float* __restrict__ pcf){
    int gt = blockIdx.x*blockDim.x + threadIdx.x;
    if (gt < PP){ g_rowbest[gt] = 0ull; g_colbest[gt] = 0ull; }
    int warp = gt >> 5;
    int lane = threadIdx.x & 31;
    if (warp >= 2*PP) return;
    const float* src = (warp < PP) ? imf : pcf;
    float* dst       = (warp < PP) ? g_nimf : g_npcf;
    int r = (warp < PP) ? warp : warp - PP;
    float4 v = ((const float4*)(src + (size_t)r*CC))[lane];
    float ss = v.x*v.x + v.y*v.y + v.z*v.z + v.w*v.w;
    #pragma unroll
    for (int o=16;o;o>>=1) ss += __shfl_xor_sync(0xffffffffu, ss, o);
    float inv = 1.0f / fmaxf(sqrtf(ss), 1e-12f);
    v.x*=inv; v.y*=inv; v.z*=inv; v.w*=inv;
    ((float4*)(dst + (size_t)r*CC))[lane] = v;
}

// ---------------- K2: tf32 hi/lo split into mma-fragment layout + pts4 -------
__global__ __launch_bounds__(256) void k_pack(const float* __restrict__ pts){
    int b = blockIdx.x;
    int tid = threadIdx.x;
    if (b < PP/16){
        int mt = b;
        #pragma unroll
        for (int s = tid; s < 512; s += 256){
            int kt = s >> 5, lane = s & 31;
            int g = lane >> 2, q = lane & 3;
            const float* base = g_nimf + (size_t)(mt*16)*CC + kt*8;
            float x0 = base[g*CC + q];
            float x1 = base[(g+8)*CC + q];
            float x2 = base[g*CC + q + 4];
            float x3 = base[(g+8)*CC + q + 4];
            float4 hi, lo;
            hi.x = tf32r(x0); lo.x = tf32r(x0 - hi.x);
            hi.y = tf32r(x1); lo.y = tf32r(x1 - hi.y);
            hi.z = tf32r(x2); lo.z = tf32r(x2 - hi.z);
            hi.w = tf32r(x3); lo.w = tf32r(x3 - hi.w);
            int o = (mt*16 + kt)*32 + lane;
            ((float4*)g_ahi)[o] = hi;
            ((float4*)g_alo)[o] = lo;
        }
    } else if (b < PP/16 + PP/8){
        int nt = b - PP/16;
        #pragma unroll
        for (int s = tid; s < 512; s += 256){
            int kt = s >> 5, lane = s & 31;
            int g = lane >> 2, q = lane & 3;
            const float* base = g_npcf + (size_t)(nt*8 + g)*CC + kt*8;
            float x0 = base[q], x1 = base[q+4];
            float2 hi, lo;
            hi.x = tf32r(x0); lo.x = tf32r(x0 - hi.x);
            hi.y = tf32r(x1); lo.y = tf32r(x1 - hi.y);
            int o = (nt*16 + kt)*32 + lane;
            ((float2*)g_bhi)[o] = hi;
            ((float2*)g_blo)[o] = lo;
        }
    } else {
        int i = (b - PP/16 - PP/8)*256 + tid;
        if (i < PP){
            float4 p; p.x = pts[3*i]; p.y = pts[3*i+1]; p.z = pts[3*i+2]; p.w = 0.f;
            g_pts4[i] = p;
        }
    }
}

// ---------------- K3: FUSED 3xTF32 GEMM (3-stage, R12-exact) + KNN -----------
// Grid 2240: every 7 consecutive block ids = 5 gemm-role + 2 knn-role blocks,
// interleaving tensor-bound and ALU-bound CTAs on each SM for pipe overlap.
__device__ __forceinline__ void mma_tf32(float& d0, float& d1, float& d2, float& d3,
    unsigned a0, unsigned a1, unsigned a2, unsigned a3, unsigned b0, unsigned b1){
    asm volatile("mma.sync.aligned.m16n8k8.row.col.f32.tf32.tf32.f32 "
        "{%0,%1,%2,%3},{%4,%5,%6,%7},{%8,%9},{%0,%1,%2,%3};\n"
        : "+f"(d0),"+f"(d1),"+f"(d2),"+f"(d3)
        : "r"(a0),"r"(a1),"r"(a2),"r"(a3),"r"(b0),"r"(b1));
}

#define STAGE_BYTES 32768u   // A 16KB (1024 float4) + B 16KB (2048 float2)
#define STAGE_FLOATS 8192

__device__ __forceinline__ void gemm_issue(unsigned sbase, int st, int c,
                                           int r0, int c0, int tid){
    const float* Ap = (c < 8) ? g_ahi : g_alo;             // hi,hi,lo
    const float* Bp = (c >= 4 && c < 8) ? g_blo : g_bhi;   // hi,lo,hi
    int kt0 = (c & 3)*4;
    int mt0 = r0 >> 4;
    int nt0 = c0 >> 3;
    unsigned abase = sbase + (unsigned)st*STAGE_BYTES;
    unsigned bbase = abase + 16384u;
    #pragma unroll
    for (int it=0; it<4; it++){
        int idx = it*256 + tid;
        int ga = (mt0 + (idx>>7))*512 + kt0*32 + (idx & 127);      // float4 units
        cpasync16(abase + idx*16, Ap + (size_t)ga*4);
        int gb = (nt0 + (idx>>6))*512 + kt0*32 + ((idx & 63)*2);   // float2 units
        cpasync16(bbase + idx*16, Bp + (size_t)gb*2);
    }
    asm volatile("cp.async.commit_group;\n");
}

__device__ void gemm_role(float* dynsmem, int gidx){
    unsigned sbase = (unsigned)__cvta_generic_to_shared(dynsmem);
    int tid = threadIdx.x;
    int lane = tid & 31;
    int warp = tid >> 5;
    int wm = warp >> 2, wn = warp & 3;
    int g = lane >> 2, q = lane & 3;
    int r0 = (gidx / 40)*128, c0 = (gidx % 40)*128;
    int mb = wm*64, nb = wn*32;

    float acc[4][4][4];
    #pragma unroll
    for (int a=0;a<4;a++)
        #pragma unroll
        for (int b=0;b<4;b++)
            #pragma unroll
            for (int i2=0;i2<4;i2++) acc[a][b][i2] = 0.f;

    gemm_issue(sbase, 0, 0, r0, c0, tid);
    gemm_issue(sbase, 1, 1, r0, c0, tid);
    gemm_issue(sbase, 2, 2, r0, c0, tid);

    #pragma unroll 1
    for (int c=0;c<12;c++){
        if (c <= 9)       asm volatile("cp.async.wait_group 2;\n");
        else if (c == 10) asm volatile("cp.async.wait_group 1;\n");
        else              asm volatile("cp.async.wait_group 0;\n");
        __syncthreads();
        const float4* sA = (const float4*)(dynsmem + (c % 3)*STAGE_FLOATS);
        const float2* sB = (const float2*)(dynsmem + (c % 3)*STAGE_FLOATS + 4096);
        #pragma unroll
        for (int ks=0; ks<4; ks++){
            float4 a4[4]; float2 b2[4];
            #pragma unroll
            for (int t=0;t<4;t++){
                a4[t] = sA[((wm*4 + t)*4 + ks)*32 + lane];
                b2[t] = sB[((wn*4 + t)*4 + ks)*32 + lane];
            }
            #pragma unroll
            for (int tm=0; tm<4; tm++)
                #pragma unroll
                for (int tn=0; tn<4; tn++)
                    mma_tf32(acc[tm][tn][0], acc[tm][tn][1], acc[tm][tn][2], acc[tm][tn][3],
                             __float_as_uint(a4[tm].x), __float_as_uint(a4[tm].y),
                             __float_as_uint(a4[tm].z), __float_as_uint(a4[tm].w),
                             __float_as_uint(b2[tn].x), __float_as_uint(b2[tn].y));
        }
        __syncthreads();
        if (c <= 8) gemm_issue(sbase, c % 3, c + 3, r0, c0, tid);
    }

    // ---- epilogue: packed row/col argmax via shared u64 atomics ----
    unsigned long long* rowk = (unsigned long long*)dynsmem;     // 128
    unsigned long long* colk = rowk + 128;                       // 128
    if (tid < 128){ rowk[tid] = 0ull; colk[tid] = 0ull; }
    __syncthreads();

    #pragma unroll
    for (int tm=0; tm<4; tm++){
        unsigned long long klo = 0ull, khi = 0ull;
        #pragma unroll
        for (int tn=0; tn<4; tn++){
            int n0 = c0 + nb + tn*8 + 2*q;
            klo = maxull(klo, KEYPACK(acc[tm][tn][0], n0));
            klo = maxull(klo, KEYPACK(acc[tm][tn][1], n0+1));
            khi = maxull(khi, KEYPACK(acc[tm][tn][2], n0));
            khi = maxull(khi, KEYPACK(acc[tm][tn][3], n0+1));
        }
        atomicMax(&rowk[mb + tm*16 + g    ], klo);
        atomicMax(&rowk[mb + tm*16 + g + 8], khi);
    }
    #pragma unroll
    for (int tn=0; tn<4; tn++){
        unsigned long long c0k = 0ull, c1k = 0ull;
        #pragma unroll
        for (int tm=0; tm<4; tm++){
            int m0 = r0 + mb + tm*16 + g;
            c0k = maxull(c0k, KEYPACK(acc[tm][tn][0], m0));
            c0k = maxull(c0k, KEYPACK(acc[tm][tn][2], m0+8));
            c1k = maxull(c1k, KEYPACK(acc[tm][tn][1], m0));
            c1k = maxull(c1k, KEYPACK(acc[tm][tn][3], m0+8));
        }
        atomicMax(&colk[nb + tn*8 + 2*q    ], c0k);
        atomicMax(&colk[nb + tn*8 + 2*q + 1], c1k);
    }
    __syncthreads();
    if (tid < 128) atomicMax(&g_rowbest[r0+tid], rowk[tid]);
    else           atomicMax(&g_colbest[c0+tid-128], colk[tid-128]);
}

// knn role: R12 warp-per-row version (proven 86us, bit-exact keys)
__device__ void knn_role(int kidx){
    int warp = threadIdx.x >> 5;
    int lane = threadIdx.x & 31;
    int i = kidx*8 + warp;
    float4 cp = g_pts4[i];
    float px = cp.x, py = cp.y, pz = cp.z;

    unsigned long long k0=SENTK,k1=SENTK,k2=SENTK,k3=SENTK;
    for (int j=lane; j<PP; j+=32){
        float4 pv = g_pts4[j];
        float dx = pv.x-px, dy = pv.y-py, dz = pv.z-pz;
        float d2 = fmaf(dx,dx, fmaf(dy,dy, dz*dz));
        unsigned long long key = ((unsigned long long)__float_as_uint(d2) << 32) | (unsigned)j;
        if (key < k3){
            k3 = key;
            if (k3 < k2){ unsigned long long t=k2; k2=k3; k3=t; }
            if (k2 < k1){ unsigned long long t=k1; k1=k2; k2=t; }
            if (k1 < k0){ unsigned long long t=k0; k0=k1; k1=t; }
        }
    }

    #pragma unroll 1
    for (int t=0; t<KKN; t++){
        unsigned long long m = k0;
        #pragma unroll
        for (int o=16;o;o>>=1) m = minull(m, __shfl_xor_sync(0xffffffffu, m, o));
        unsigned own = __ballot_sync(0xffffffffu, k0 == m);
        if (lane == 0) g_nb[i*KKN + t] = (int)(unsigned)m;
        if (own & (1u << lane)){
            k0 = k1; k1 = k2; k2 = k3; k3 = SENTK;
            if (k0 == SENTK){
                #pragma unroll 1
                for (int j=lane; j<PP; j+=32){
                    float4 pv = g_pts4[j];
                    float dx = pv.x-px, dy = pv.y-py, dz = pv.z-pz;
                    float d2 = fmaf(dx,dx, fmaf(dy,dy, dz*dz));
                    unsigned long long key = ((unsigned long long)__float_as_uint(d2) << 32) | (unsigned)j;
                    if (key > m && key < k3){
                        k3 = key;
                        if (k3 < k2){ unsigned long long q=k2; k2=k3; k3=q; }
                        if (k2 < k1){ unsigned long long q=k1; k1=k2; k2=q; }
                        if (k1 < k0){ unsigned long long q=k0; k0=k1; k1=q; }
                    }
                }
            }
        }
    }
}

__global__ __launch_bounds__(256,2) void k_work(){
    extern __shared__ __align__(16) float dynsmem[];
    int bid = blockIdx.x;
    int grp = bid / 7, r = bid % 7;     // 2240 blocks = 320 groups of (5 gemm + 2 knn)
    if (r < 5) gemm_role(dynsmem, grp*5 + r);
    else       knn_role(grp*2 + (r - 5));
}

// ---------------- K5: merged im/pc branch (warp per row) ---------------------
__global__ __launch_bounds__(128) void k_spot(float* __restrict__ sel_out){
    int gwarp = (blockIdx.x*blockDim.x + threadIdx.x) >> 5;
    int lane = threadIdx.x & 31;
    if (gwarp < PP){
        int p = gwarp, h = p >> 7, w = p & 127;   // WW == 128
        float4 cf = ((const float4*)(g_nimf + (size_t)p*CC))[lane];
        float acc[KKN];
        #pragma unroll
        for (int k=0; k<KKN; k++){
            int di = k/5 - 2, dj = k%5 - 2;
            int hh = iclamp(h+di, 0, HH-1), ww = iclamp(w+dj, 0, WW-1);
            float4 nf = ((const float4*)(g_nimf + (size_t)(hh*WW+ww)*CC))[lane];
            acc[k] = fmaf(cf.x,nf.x, fmaf(cf.y,nf.y, fmaf(cf.z,nf.z, cf.w*nf.w)));
        }
        #pragma unroll
        for (int o=16;o;o>>=1){
            #pragma unroll
            for (int k=0; k<KKN; k++) acc[k] += __shfl_xor_sync(0xffffffffu, acc[k], o);
        }
        float v = -FMAXV;
        #pragma unroll
        for (int k=0; k<KKN; k++) if (lane == k) v = acc[k];

        float m = v;
        #pragma unroll
        for (int o=16;o;o>>=1) m = fmaxf(m, __shfl_xor_sync(0xffffffffu, m, o));
        float e = (lane < KKN) ? expf(v - m) : 0.f;
        float su = e;
        #pragma unroll
        for (int o=16;o;o>>=1) su += __shfl_xor_sync(0xffffffffu, su, o);
        float soft = e / su;

        int di = lane/5 - 2, dj = lane%5 - 2;
        float selv = NEGV;
        if (lane < KKN){
            bool inb = ((unsigned)(h+di) < (unsigned)HH) && ((unsigned)(w+dj) < (unsigned)WW);
            int hh = iclamp(h+di, 0, HH-1), ww = iclamp(w+dj, 0, WW-1);
            float conf = sort2f((unsigned)(g_rowbest[hh*WW+ww] >> 32));
            selv = inb ? soft*conf : NEGV;
            sel_out[(size_t)lane*PP + p] = selv;
        }
        float cand = (lane < KKN && lane != 12) ? selv : -FMAXV;
        #pragma unroll 1
        for (int s=0; s<SPOTN; s++){
            int kk;
            if (s == 0){
                kk = 12;
            } else {
                unsigned long long key = ((unsigned long long)f2sort(cand) << 32) | (unsigned)(31 - lane);
                #pragma unroll
                for (int o=16;o;o>>=1){
                    unsigned long long ok = __shfl_xor_sync(0xffffffffu, key, o);
                    if (ok > key) key = ok;
                }
                kk = 31 - (int)(key & 0xffffffffull);
                if (lane == kk) cand = -FMAXV;
            }
            int q = (h + kk/5 - 2)*WW + (w + kk%5 - 2);
            int sd = (int)(~(unsigned)g_rowbest[q]);
            if (lane < KKN) g_spot_im[(size_t)p*125 + s*25 + lane] = g_nb[sd*KKN + lane];
        }
    } else {
        int p = gwarp - PP;
        float4 cf = ((const float4*)(g_npcf + (size_t)p*CC))[lane];
        int nbk[KKN];
        #pragma unroll
        for (int k=0; k<KKN; k++) nbk[k] = g_nb[p*KKN + k];
        float acc[KKN];
        #pragma unroll
        for (int k=0; k<KKN; k++){
            float4 nf = ((const float4*)(g_npcf + (size_t)nbk[k]*CC))[lane];
            acc[k] = fmaf(cf.x,nf.x, fmaf(cf.y,nf.y, fmaf(cf.z,nf.z, cf.w*nf.w)));
        }
        #pragma unroll
        for (int o=16;o;o>>=1){
            #pragma unroll
            for (int k=0; k<KKN; k++) acc[k] += __shfl_xor_sync(0xffffffffu, acc[k], o);
        }
        float v = -FMAXV; int myq = 0;
        #pragma unroll
        for (int k=0; k<KKN; k++) if (lane == k){ v = acc[k]; myq = nbk[k]; }

        float m = v;
        #pragma unroll
        for (int o=16;o;o>>=1) m = fmaxf(m, __shfl_xor_sync(0xffffffffu, m, o));
        float e = (lane < KKN) ? expf(v - m) : 0.f;
        float su = e;
        #pragma unroll
        for (int o=16;o;o>>=1) su += __shfl_xor_sync(0xffffffffu, su, o);
        float soft = e / su;

        float selv = NEGV;
        if (lane < KKN && lane != 0)
            selv = soft * sort2f((unsigned)(g_colbest[myq] >> 32));
        float cand = (lane >= 1 && lane < KKN) ? selv : -FMAXV;
        #pragma unroll 1
        for (int s=0; s<SPOTN; s++){
            int kk;
            if (s == 0){
                kk = 0;
            } else {
                unsigned long long key = ((unsigned long long)f2sort(cand) << 32) | (unsigned)(31 - lane);
                #pragma unroll
                for (int o=16;o;o>>=1){
                    unsigned long long ok = __shfl_xor_sync(0xffffffffu, key, o);
                    if (ok > key) key = ok;
                }
                kk = 31 - (int)(key & 0xffffffffull);
                if (lane == kk) cand = -FMAXV;
            }
            int qq = __shfl_sync(0xffffffffu, myq, kk);
            int pix = (int)(~(unsigned)g_colbest[qq]);
            int pr = pix >> 7, pc = pix & 127;
            if (lane < KKN){
                int rr = iclamp(pr + lane/5 - 2, 0, HH-1);
                int cc = iclamp(pc + lane%5 - 2, 0, WW-1);
                g_spot_pc[(size_t)p*125 + s*25 + lane] = rr*WW + cc;
            }
        }
    }
}

// ---------------- K6: scatter mask + stable top-125, warp per row ------------
__global__ __launch_bounds__(256) void k_mask(float* __restrict__ mask_im,
                                              float* __restrict__ idx_im,
                                              float* __restrict__ idx_pc,
                                              float* __restrict__ mask_pc){
    __shared__ unsigned bm[8][160];
    int which = blockIdx.y;
    const int* spot = which ? g_spot_pc : g_spot_im;
    float* omask = which ? mask_pc : mask_im;
    float* oidx  = which ? idx_pc  : idx_im;
    int wid  = threadIdx.x >> 5;
    int lane = threadIdx.x & 31;
    int row = blockIdx.x*8 + wid;

    #pragma unroll
    for (int w=0; w<5; w++) bm[wid][lane*5 + w] = 0u;
    __syncwarp();
    for (int i=lane; i<125; i+=32){
        int v = spot[(size_t)row*125 + i];
        atomicOr(&bm[wid][v>>5], 1u << (v & 31));
    }
    __syncwarp();

    unsigned wds[5]; int cnt = 0;
    #pragma unroll
    for (int w=0; w<5; w++){ wds[w] = bm[wid][lane*5 + w]; cnt += __popc(wds[w]); }
    int incl = cnt;
    #pragma unroll
    for (int o=1;o<32;o<<=1){
        int t = __shfl_up_sync(0xffffffffu, incl, o);
        if (lane >= o) incl += t;
    }
    int excl = incl - cnt;
    int total = __shfl_sync(0xffffffffu, incl, 31);

    float* om = omask + (size_t)row*125;
    float* oi = oidx  + (size_t)row*125;
    int slot = excl;
    #pragma unroll
    for (int w=0; w<5; w++){
        unsigned x = wds[w];
        int base = (lane*5 + w)*32;
        while (x){
            int b = __ffs(x) - 1; x &= x - 1;
            oi[slot] = (float)(base + b); om[slot] = 1.f; slot++;
        }
    }
    int arank = 160*lane - excl;
    slot = total + arank;
    if (slot < 125){
        #pragma unroll
        for (int w=0; w<5 && slot < 125; w++){
            unsigned y = ~wds[w];
            int base = (lane*5 + w)*32;
            while (y && slot < 125){
                int b = __ffs(y) - 1; y &= y - 1;
                oi[slot] = (float)(base + b); om[slot] = 0.f; slot++;
            }
        }
    }
}

// ---------------- launch ------------------------------------------------------
extern "C" void kernel_launch(void* const* d_in, const int* in_sizes, int n_in,
                              void* d_out, int out_size){
    const float* imf = (const float*)d_in[0];
    const float* pcf = (const float*)d_in[1];
    const float* pts = (const float*)d_in[2];
    float* out = (float*)d_out;

    float* sel_out     = out;                       // 25*5120
    float* mask_out    = out + 25*PP;               // 5120*125
    float* idx_out     = out + 25*PP + 125*PP;      // 5120*125
    float* idx_pc_out  = out + 25*PP + 2*125*PP;    // 5120*125
    float* mask_pc_out = out + 25*PP + 3*125*PP;    // 5120*125

    cudaFuncSetAttribute(k_work, cudaFuncAttributeMaxDynamicSharedMemorySize, 98304);

    // NOTE: launch order chosen so ncu's captured launch (4th) is k_spot.
    k_norm<<<(2*PP*32 + 255)/256, 256>>>(imf, pcf);                   // 1
    k_pack<<<PP/16 + PP/8 + (PP+255)/256, 256>>>(pts);                // 2
    k_work<<<2240, 256, 98304>>>();                                   // 3 (gemm+knn fused)
    k_spot<<<2*PP/4, 128>>>(sel_out);                                 // 4 <- profiled
    k_mask<<<dim3(PP/8, 2), 256>>>(mask_out, idx_out, idx_pc_out, mask_pc_out); // 5
}

// round 17
// speedup vs baseline: 1.3844x; 1.3844x over previous
#include <cuda_runtime.h>
#include <cuda_fp16.h>

#define HH 40
#define WW 128
#define PP 5120
#define CC 128
#define KKN 25
#define SPOTN 5
#define NEGV (-1e8f)
#define FMAXV 3.402823466e38f
#define SENTK 0xffffffffffffffffull

// ---------------- scratch (device globals; no allocations allowed) ----------
__device__ float g_nimf[PP*CC];
__device__ float g_npcf[PP*CC];
__device__ float g_ahi[PP*CC];   // A fp16 fragments (imf) hi  (uint4 view)
__device__ float g_alo[PP*CC];   // A fragments lo
__device__ float g_bhi[PP*CC];   // B fp16 fragments (pcf) hi  (uint2 view)
__device__ float g_blo[PP*CC];   // B fragments lo
__device__ float4 g_pts4[PP];    // padded points for vectorized knn
__device__ int   g_nb[PP*KKN];
__device__ unsigned long long g_rowbest[PP];
__device__ unsigned long long g_colbest[PP];
__device__ int   g_spot_im[PP*125];
__device__ int   g_spot_pc[PP*125];

__device__ __forceinline__ unsigned f2sort(float f){
    unsigned b = __float_as_uint(f);
    return (b & 0x80000000u) ? ~b : (b | 0x80000000u);
}
__device__ __forceinline__ float sort2f(unsigned u){
    unsigned b = (u & 0x80000000u) ? (u & 0x7fffffffu) : ~u;
    return __uint_as_float(b);
}
__device__ __forceinline__ int iclamp(int v, int lo, int hi){
    return v < lo ? lo : (v > hi ? hi : v);
}
__device__ __forceinline__ unsigned long long maxull(unsigned long long a, unsigned long long b){
    return a > b ? a : b;
}
__device__ __forceinline__ unsigned long long minull(unsigned long long a, unsigned long long b){
    return a < b ? a : b;
}
__device__ __forceinline__ void cpasync16(unsigned s, const void* g){
    asm volatile("cp.async.cg.shared.global [%0], [%1], 16;\n" :: "r"(s), "l"(g));
}
__device__ __forceinline__ void split2(float x, float y, unsigned& hi, unsigned& lo){
    __half hx = __float2half_rn(x), hy = __float2half_rn(y);
    float lxf = x - __half2float(hx), lyf = y - __half2float(hy);
    __half lx = __float2half_rn(lxf), ly = __float2half_rn(lyf);
    hi = (unsigned)__half_as_ushort(hx) | ((unsigned)__half_as_ushort(hy) << 16);
    lo = (unsigned)__half_as_ushort(lx) | ((unsigned)__half_as_ushort(ly) << 16);
}
#define KEYPACK(v,n) ((((unsigned long long)f2sort(v)) << 32) | (unsigned)(~(n)))

// ---------------- K1: L2 normalize both + argmax init ------------------------
__global__ __launch_bounds__(256) void k_norm(const float* __restrict__ imf,
                                              const float* __restrict__ pcf){
    int gt = blockIdx.x*blockDim.x + threadIdx.x;
    if (gt < PP){ g_rowbest[gt] = 0ull; g_colbest[gt] = 0ull; }
    int warp = gt >> 5;
    int lane = threadIdx.x & 31;
    if (warp >= 2*PP) return;
    const float* src = (warp < PP) ? imf : pcf;
    float* dst       = (warp < PP) ? g_nimf : g_npcf;
    int r = (warp < PP) ? warp : warp - PP;
    float4 v = ((const float4*)(src + (size_t)r*CC))[lane];
    float ss = v.x*v.x + v.y*v.y + v.z*v.z + v.w*v.w;
    #pragma unroll
    for (int o=16;o;o>>=1) ss += __shfl_xor_sync(0xffffffffu, ss, o);
    float inv = 1.0f / fmaxf(sqrtf(ss), 1e-12f);
    v.x*=inv; v.y*=inv; v.z*=inv; v.w*=inv;
    ((float4*)(dst + (size_t)r*CC))[lane] = v;
}

// ---------------- K2: fp16 hi/lo split into m16n8k16 fragment layout + pts4 --
// A (imf): per (mt, kt16) 16x16 tile, lane(g=l>>2,q=l&3) holds uint4 =
//   [h2(A[g][2q],A[g][2q+1]), h2(A[g+8][2q],A[g+8][2q+1]),
//    h2(A[g][2q+8],A[g][2q+9]), h2(A[g+8][2q+8],A[g+8][2q+9])]  (rows/cols
//   relative to tile origin mt*16 / kt*16), at uint4 idx (mt*8+kt)*32+lane.
// B (pcf): per (nt, kt16) 8x16 tile, lane holds uint2 =
//   [h2(B[n=g][2q],B[g][2q+1]), h2(B[g][2q+8],B[g][2q+9])] at uint2 idx
//   (nt*8+kt)*32+lane.  (mma row.col: B fragment rows=k, col=g.)
__global__ __launch_bounds__(256) void k_pack(const float* __restrict__ pts){
    int b = blockIdx.x;
    int tid = threadIdx.x;
    if (b < PP/16){
        int mt = b;
        int kt = tid >> 5, lane = tid & 31;
        int g = lane >> 2, q = lane & 3;
        const float* r0p = g_nimf + (size_t)(mt*16 + g)*CC + kt*16;
        const float* r1p = r0p + 8*CC;
        uint4 hi, lo;
        split2(r0p[2*q],   r0p[2*q+1], hi.x, lo.x);
        split2(r1p[2*q],   r1p[2*q+1], hi.y, lo.y);
        split2(r0p[2*q+8], r0p[2*q+9], hi.z, lo.z);
        split2(r1p[2*q+8], r1p[2*q+9], hi.w, lo.w);
        int o = (mt*8 + kt)*32 + lane;
        ((uint4*)g_ahi)[o] = hi;
        ((uint4*)g_alo)[o] = lo;
    } else if (b < PP/16 + PP/8){
        int nt = b - PP/16;
        int kt = tid >> 5, lane = tid & 31;
        int g = lane >> 2, q = lane & 3;
        const float* np = g_npcf + (size_t)(nt*8 + g)*CC + kt*16;
        uint2 hi, lo;
        split2(np[2*q],   np[2*q+1], hi.x, lo.x);
        split2(np[2*q+8], np[2*q+9], hi.y, lo.y);
        int o = (nt*8 + kt)*32 + lane;
        ((uint2*)g_bhi)[o] = hi;
        ((uint2*)g_blo)[o] = lo;
    } else {
        int i = (b - PP/16 - PP/8)*256 + tid;
        if (i < PP){
            float4 p; p.x = pts[3*i]; p.y = pts[3*i+1]; p.z = pts[3*i+2]; p.w = 0.f;
            g_pts4[i] = p;
        }
    }
}

// ---------------- K3: 3xFP16 GEMM (m16n8k16), 3-stage cp.async ---------------
// S = nimf @ npcf^T as Ahi*Bhi + Ahi*Blo + Alo*Bhi, fp32 accum.
__device__ __forceinline__ void mma_f16(float& d0, float& d1, float& d2, float& d3,
    unsigned a0, unsigned a1, unsigned a2, unsigned a3, unsigned b0, unsigned b1){
    asm volatile("mma.sync.aligned.m16n8k16.row.col.f32.f16.f16.f32 "
        "{%0,%1,%2,%3},{%4,%5,%6,%7},{%8,%9},{%0,%1,%2,%3};\n"
        : "+f"(d0),"+f"(d1),"+f"(d2),"+f"(d3)
        : "r"(a0),"r"(a1),"r"(a2),"r"(a3),"r"(b0),"r"(b1));
}

#define STG_BYTES 16384u    // A 8KB (512 uint4) + B 8KB (1024 uint2)
#define STG_FLOATS 4096

// stage st <- virtual chunk c (pass = c>>2 picks hi/lo arrays, kc = c&3).
__device__ __forceinline__ void gemm_issue(unsigned sbase, int st, int c,
                                           int r0, int c0, int tid){
    const uint4* Ap = (const uint4*)((c < 8) ? g_ahi : g_alo);           // hi,hi,lo
    const uint4* Bp = (const uint4*)((c >= 4 && c < 8) ? g_blo : g_bhi); // hi,lo,hi
    int kc = (c & 3)*2;      // kt16 base (2 per chunk)
    int mt0 = r0 >> 4;
    int nt0 = c0 >> 3;
    unsigned abase = sbase + (unsigned)st*STG_BYTES;
    unsigned bbase = abase + 8192u;
    #pragma unroll
    for (int it=0; it<4; it++){
        int idx = it*256 + tid;                    // 0..1023 16B units
        if (idx < 512){
            int mtile = idx >> 6, rem = idx & 63;  // ktl*32+lane
            int ga = ((mt0 + mtile)*8 + kc + (rem>>5))*32 + (rem & 31);
            cpasync16(abase + idx*16, Ap + ga);
        } else {
            int u = idx - 512;
            int ntile = u >> 5, rem = u & 31;      // ktl*16+pair
            int gb = ((nt0 + ntile)*8 + kc + (rem>>4))*16 + (rem & 15);
            cpasync16(bbase + u*16, Bp + gb);
        }
    }
    asm volatile("cp.async.commit_group;\n");
}

__global__ __launch_bounds__(256,2) void k_gemm(){
    extern __shared__ __align__(16) float dynsmem[];
    unsigned sbase = (unsigned)__cvta_generic_to_shared(dynsmem);
    int tid = threadIdx.x;
    int lane = tid & 31;
    int warp = tid >> 5;
    int wm = warp >> 2, wn = warp & 3;
    int g = lane >> 2, q = lane & 3;
    int r0 = blockIdx.y*128, c0 = blockIdx.x*128;
    int mb = wm*64, nb = wn*32;

    float acc[4][4][4];
    #pragma unroll
    for (int a=0;a<4;a++)
        #pragma unroll
        for (int b=0;b<4;b++)
            #pragma unroll
            for (int i2=0;i2<4;i2++) acc[a][b][i2] = 0.f;

    gemm_issue(sbase, 0, 0, r0, c0, tid);
    gemm_issue(sbase, 1, 1, r0, c0, tid);
    gemm_issue(sbase, 2, 2, r0, c0, tid);

    #pragma unroll 1
    for (int c=0;c<12;c++){
        if (c <= 9)       asm volatile("cp.async.wait_group 2;\n");
        else if (c == 10) asm volatile("cp.async.wait_group 1;\n");
        else              asm volatile("cp.async.wait_group 0;\n");
        __syncthreads();
        const uint4* sA = (const uint4*)(dynsmem + (c % 3)*STG_FLOATS);
        const uint2* sB = (const uint2*)(dynsmem + (c % 3)*STG_FLOATS + 2048);
        #pragma unroll
        for (int ktl=0; ktl<2; ktl++){
            uint4 a4[4]; uint2 b2[4];
            #pragma unroll
            for (int t=0;t<4;t++){
                a4[t] = sA[((wm*4 + t)*2 + ktl)*32 + lane];
                b2[t] = sB[((wn*4 + t)*2 + ktl)*32 + lane];
            }
            #pragma unroll
            for (int tm=0; tm<4; tm++)
                #pragma unroll
                for (int tn=0; tn<4; tn++)
                    mma_f16(acc[tm][tn][0], acc[tm][tn][1], acc[tm][tn][2], acc[tm][tn][3],
                            a4[tm].x, a4[tm].y, a4[tm].z, a4[tm].w,
                            b2[tn].x, b2[tn].y);
        }
        __syncthreads();
        if (c <= 8) gemm_issue(sbase, c % 3, c + 3, r0, c0, tid);
    }

    // ---- epilogue: packed row/col argmax via shared u64 atomics ----
    unsigned long long* rowk = (unsigned long long*)dynsmem;     // 128
    unsigned long long* colk = rowk + 128;                       // 128
    if (tid < 128){ rowk[tid] = 0ull; colk[tid] = 0ull; }
    __syncthreads();

    #pragma unroll
    for (int tm=0; tm<4; tm++){
        unsigned long long klo = 0ull, khi = 0ull;
        #pragma unroll
        for (int tn=0; tn<4; tn++){
            int n0 = c0 + nb + tn*8 + 2*q;
            klo = maxull(klo, KEYPACK(acc[tm][tn][0], n0));
            klo = maxull(klo, KEYPACK(acc[tm][tn][1], n0+1));
            khi = maxull(khi, KEYPACK(acc[tm][tn][2], n0));
            khi = maxull(khi, KEYPACK(acc[tm][tn][3], n0+1));
        }
        atomicMax(&rowk[mb + tm*16 + g    ], klo);
        atomicMax(&rowk[mb + tm*16 + g + 8], khi);
    }
    #pragma unroll
    for (int tn=0; tn<4; tn++){
        unsigned long long c0k = 0ull, c1k = 0ull;
        #pragma unroll
        for (int tm=0; tm<4; tm++){
            int m0 = r0 + mb + tm*16 + g;
            c0k = maxull(c0k, KEYPACK(acc[tm][tn][0], m0));
            c0k = maxull(c0k, KEYPACK(acc[tm][tn][2], m0+8));
            c1k = maxull(c1k, KEYPACK(acc[tm][tn][1], m0));
            c1k = maxull(c1k, KEYPACK(acc[tm][tn][3], m0+8));
        }
        atomicMax(&colk[nb + tn*8 + 2*q    ], c0k);
        atomicMax(&colk[nb + tn*8 + 2*q + 1], c1k);
    }
    __syncthreads();
    if (tid < 128) atomicMax(&g_rowbest[r0+tid], rowk[tid]);
    else           atomicMax(&g_colbest[c0+tid-128], colk[tid-128]);
}

// ---------------- K4: knn — R12 version (proven 86us, bit-exact) -------------
#define KNN_WARPS 8
__global__ __launch_bounds__(KNN_WARPS*32) void k_knn(){
    int warp = threadIdx.x >> 5;
    int lane = threadIdx.x & 31;
    int i = blockIdx.x*KNN_WARPS + warp;
    float4 cp = g_pts4[i];
    float px = cp.x, py = cp.y, pz = cp.z;

    unsigned long long k0=SENTK,k1=SENTK,k2=SENTK,k3=SENTK;
    for (int j=lane; j<PP; j+=32){
        float4 pv = g_pts4[j];
        float dx = pv.x-px, dy = pv.y-py, dz = pv.z-pz;
        float d2 = fmaf(dx,dx, fmaf(dy,dy, dz*dz));
        unsigned long long key = ((unsigned long long)__float_as_uint(d2) << 32) | (unsigned)j;
        if (key < k3){
            k3 = key;
            if (k3 < k2){ unsigned long long t=k2; k2=k3; k3=t; }
            if (k2 < k1){ unsigned long long t=k1; k1=k2; k2=t; }
            if (k1 < k0){ unsigned long long t=k0; k0=k1; k1=t; }
        }
    }

    #pragma unroll 1
    for (int t=0; t<KKN; t++){
        unsigned long long m = k0;
        #pragma unroll
        for (int o=16;o;o>>=1) m = minull(m, __shfl_xor_sync(0xffffffffu, m, o));
        unsigned own = __ballot_sync(0xffffffffu, k0 == m);
        if (lane == 0) g_nb[i*KKN + t] = (int)(unsigned)m;
        if (own & (1u << lane)){
            k0 = k1; k1 = k2; k2 = k3; k3 = SENTK;
            if (k0 == SENTK){
                #pragma unroll 1
                for (int j=lane; j<PP; j+=32){
                    float4 pv = g_pts4[j];
                    float dx = pv.x-px, dy = pv.y-py, dz = pv.z-pz;
                    float d2 = fmaf(dx,dx, fmaf(dy,dy, dz*dz));
                    unsigned long long key = ((unsigned long long)__float_as_uint(d2) << 32) | (unsigned)j;
                    if (key > m && key < k3){
                        k3 = key;
                        if (k3 < k2){ unsigned long long q=k2; k2=k3; k3=q; }
                        if (k2 < k1){ unsigned long long q=k1; k1=k2; k2=q; }
                        if (k1 < k0){ unsigned long long q=k0; k0=k1; k1=q; }
                    }
                }
            }
        }
    }
}

// ---------------- K5: merged im/pc branch (warp per row) ---------------------
__global__ __launch_bounds__(128) void k_spot(float* __restrict__ sel_out){
    int gwarp = (blockIdx.x*blockDim.x + threadIdx.x) >> 5;
    int lane = threadIdx.x & 31;
    if (gwarp < PP){
        int p = gwarp, h = p >> 7, w = p & 127;   // WW == 128
        float4 cf = ((const float4*)(g_nimf + (size_t)p*CC))[lane];
        float acc[KKN];
        #pragma unroll
        for (int k=0; k<KKN; k++){
            int di = k/5 - 2, dj = k%5 - 2;
            int hh = iclamp(h+di, 0, HH-1), ww = iclamp(w+dj, 0, WW-1);
            float4 nf = ((const float4*)(g_nimf + (size_t)(hh*WW+ww)*CC))[lane];
            acc[k] = fmaf(cf.x,nf.x, fmaf(cf.y,nf.y, fmaf(cf.z,nf.z, cf.w*nf.w)));
        }
        #pragma unroll
        for (int o=16;o;o>>=1){
            #pragma unroll
            for (int k=0; k<KKN; k++) acc[k] += __shfl_xor_sync(0xffffffffu, acc[k], o);
        }
        float v = -FMAXV;
        #pragma unroll
        for (int k=0; k<KKN; k++) if (lane == k) v = acc[k];

        float m = v;
        #pragma unroll
        for (int o=16;o;o>>=1) m = fmaxf(m, __shfl_xor_sync(0xffffffffu, m, o));
        float e = (lane < KKN) ? expf(v - m) : 0.f;
        float su = e;
        #pragma unroll
        for (int o=16;o;o>>=1) su += __shfl_xor_sync(0xffffffffu, su, o);
        float soft = e / su;

        int di = lane/5 - 2, dj = lane%5 - 2;
        float selv = NEGV;
        if (lane < KKN){
            bool inb = ((unsigned)(h+di) < (unsigned)HH) && ((unsigned)(w+dj) < (unsigned)WW);
            int hh = iclamp(h+di, 0, HH-1), ww = iclamp(w+dj, 0, WW-1);
            float conf = sort2f((unsigned)(g_rowbest[hh*WW+ww] >> 32));
            selv = inb ? soft*conf : NEGV;
            sel_out[(size_t)lane*PP + p] = selv;
        }
        float cand = (lane < KKN && lane != 12) ? selv : -FMAXV;
        #pragma unroll 1
        for (int s=0; s<SPOTN; s++){
            int kk;
            if (s == 0){
                kk = 12;
            } else {
                unsigned long long key = ((unsigned long long)f2sort(cand) << 32) | (unsigned)(31 - lane);
                #pragma unroll
                for (int o=16;o;o>>=1){
                    unsigned long long ok = __shfl_xor_sync(0xffffffffu, key, o);
                    if (ok > key) key = ok;
                }
                kk = 31 - (int)(key & 0xffffffffull);
                if (lane == kk) cand = -FMAXV;
            }
            int q = (h + kk/5 - 2)*WW + (w + kk%5 - 2);
            int sd = (int)(~(unsigned)g_rowbest[q]);
            if (lane < KKN) g_spot_im[(size_t)p*125 + s*25 + lane] = g_nb[sd*KKN + lane];
        }
    } else {
        int p = gwarp - PP;
        float4 cf = ((const float4*)(g_npcf + (size_t)p*CC))[lane];
        int nbk[KKN];
        #pragma unroll
        for (int k=0; k<KKN; k++) nbk[k] = g_nb[p*KKN + k];
        float acc[KKN];
        #pragma unroll
        for (int k=0; k<KKN; k++){
            float4 nf = ((const float4*)(g_npcf + (size_t)nbk[k]*CC))[lane];
            acc[k] = fmaf(cf.x,nf.x, fmaf(cf.y,nf.y, fmaf(cf.z,nf.z, cf.w*nf.w)));
        }
        #pragma unroll
        for (int o=16;o;o>>=1){
            #pragma unroll
            for (int k=0; k<KKN; k++) acc[k] += __shfl_xor_sync(0xffffffffu, acc[k], o);
        }
        float v = -FMAXV; int myq = 0;
        #pragma unroll
        for (int k=0; k<KKN; k++) if (lane == k){ v = acc[k]; myq = nbk[k]; }

        float m = v;
        #pragma unroll
        for (int o=16;o;o>>=1) m = fmaxf(m, __shfl_xor_sync(0xffffffffu, m, o));
        float e = (lane < KKN) ? expf(v - m) : 0.f;
        float su = e;
        #pragma unroll
        for (int o=16;o;o>>=1) su += __shfl_xor_sync(0xffffffffu, su, o);
        float soft = e / su;

        float selv = NEGV;
        if (lane < KKN && lane != 0)
            selv = soft * sort2f((unsigned)(g_colbest[myq] >> 32));
        float cand = (lane >= 1 && lane < KKN) ? selv : -FMAXV;
        #pragma unroll 1
        for (int s=0; s<SPOTN; s++){
            int kk;
            if (s == 0){
                kk = 0;
            } else {
                unsigned long long key = ((unsigned long long)f2sort(cand) << 32) | (unsigned)(31 - lane);
                #pragma unroll
                for (int o=16;o;o>>=1){
                    unsigned long long ok = __shfl_xor_sync(0xffffffffu, key, o);
                    if (ok > key) key = ok;
                }
                kk = 31 - (int)(key & 0xffffffffull);
                if (lane == kk) cand = -FMAXV;
            }
            int qq = __shfl_sync(0xffffffffu, myq, kk);
            int pix = (int)(~(unsigned)g_colbest[qq]);
            int pr = pix >> 7, pc = pix & 127;
            if (lane < KKN){
                int rr = iclamp(pr + lane/5 - 2, 0, HH-1);
                int cc = iclamp(pc + lane%5 - 2, 0, WW-1);
                g_spot_pc[(size_t)p*125 + s*25 + lane] = rr*WW + cc;
            }
        }
    }
}

// ---------------- K6: scatter mask + stable top-125, warp per row ------------
__global__ __launch_bounds__(256) void k_mask(float* __restrict__ mask_im,
                                              float* __restrict__ idx_im,
                                              float* __restrict__ idx_pc,
                                              float* __restrict__ mask_pc){
    __shared__ unsigned bm[8][160];
    int which = blockIdx.y;
    const int* spot = which ? g_spot_pc : g_spot_im;
    float* omask = which ? mask_pc : mask_im;
    float* oidx  = which ? idx_pc  : idx_im;
    int wid  = threadIdx.x >> 5;
    int lane = threadIdx.x & 31;
    int row = blockIdx.x*8 + wid;

    #pragma unroll
    for (int w=0; w<5; w++) bm[wid][lane*5 + w] = 0u;
    __syncwarp();
    for (int i=lane; i<125; i+=32){
        int v = spot[(size_t)row*125 + i];
        atomicOr(&bm[wid][v>>5], 1u << (v & 31));
    }
    __syncwarp();

    unsigned wds[5]; int cnt = 0;
    #pragma unroll
    for (int w=0; w<5; w++){ wds[w] = bm[wid][lane*5 + w]; cnt += __popc(wds[w]); }
    int incl = cnt;
    #pragma unroll
    for (int o=1;o<32;o<<=1){
        int t = __shfl_up_sync(0xffffffffu, incl, o);
        if (lane >= o) incl += t;
    }
    int excl = incl - cnt;
    int total = __shfl_sync(0xffffffffu, incl, 31);

    float* om = omask + (size_t)row*125;
    float* oi = oidx  + (size_t)row*125;
    int slot = excl;
    #pragma unroll
    for (int w=0; w<5; w++){
        unsigned x = wds[w];
        int base = (lane*5 + w)*32;
        while (x){
            int b = __ffs(x) - 1; x &= x - 1;
            oi[slot] = (float)(base + b); om[slot] = 1.f; slot++;
        }
    }
    int arank = 160*lane - excl;
    slot = total + arank;
    if (slot < 125){
        #pragma unroll
        for (int w=0; w<5 && slot < 125; w++){
            unsigned y = ~wds[w];
            int base = (lane*5 + w)*32;
            while (y && slot < 125){
                int b = __ffs(y) - 1; y &= y - 1;
                oi[slot] = (float)(base + b); om[slot] = 0.f; slot++;
            }
        }
    }
}

// ---------------- launch ------------------------------------------------------
extern "C" void kernel_launch(void* const* d_in, const int* in_sizes, int n_in,
                              void* d_out, int out_size){
    const float* imf = (const float*)d_in[0];
    const float* pcf = (const float*)d_in[1];
    const float* pts = (const float*)d_in[2];
    float* out = (float*)d_out;

    float* sel_out     = out;                       // 25*5120
    float* mask_out    = out + 25*PP;               // 5120*125
    float* idx_out     = out + 25*PP + 125*PP;      // 5120*125
    float* idx_pc_out  = out + 25*PP + 2*125*PP;    // 5120*125
    float* mask_pc_out = out + 25*PP + 3*125*PP;    // 5120*125

    cudaFuncSetAttribute(k_gemm, cudaFuncAttributeMaxDynamicSharedMemorySize, 49152);

    // NOTE: launch order chosen so ncu's captured launch (4th) is k_gemm.
    k_norm<<<(2*PP*32 + 255)/256, 256>>>(imf, pcf);                   // 1
    k_pack<<<PP/16 + PP/8 + (PP+255)/256, 256>>>(pts);                // 2
    k_knn<<<PP/KNN_WARPS, KNN_WARPS*32>>>();                          // 3
    k_gemm<<<dim3(PP/128, PP/128), 256, 49152>>>();                   // 4 <- profiled
    k_spot<<<2*PP/4, 128>>>(sel_out);                                 // 5
    k_mask<<<dim3(PP/8, 2), 256>>>(mask_out, idx_out, idx_pc_out, mask_pc_out); // 6
}